// round 15
// baseline (speedup 1.0000x reference)
#include <cuda_runtime.h>
#include <cuda_bf16.h>
#include <cstdint>

// ---------------- problem constants ----------------
#define NPTS     16384          // 16 * 32 * 32 points
#define DIM      256            // embedding dim (channels)
#define KCODES   8192           // codebook size
#define XSTRIDE_B 262144        // 256 * 1024 floats per batch in x layout
#define SPATIAL  1024           // 32*32

// output packing (tuple order, flattened)
#define LOSS_OFF 4194304u
#define PPL_OFF  4194305u
#define EMB_OFF  4194306u
#define CS_OFF   6291458u
#define EAVG_OFF 6299650u

// margin threshold for exact-fp32 rescue (0.05 ~ 5 sigma; 0.02 leaked one flip)
#define RESCUE_EPS 0.05f

// ---------------- scratch (no allocations allowed) ----------------
__device__ int   g_idx[NPTS];
__device__ int   g_flag[NPTS];
__device__ int   g_nflag;
__device__ int   g_list[NPTS];
__device__ unsigned long long g_best[NPTS];
__device__ float g_count[KCODES];
__device__ float g_dw[KCODES * DIM];
__device__ float g_cnorm[KCODES];
__device__ float g_xnorm[NPTS];
__device__ float g_loss;
__device__ __nv_bfloat16 g_A[NPTS * DIM];     // x transposed to [n][d], bf16
__device__ __nv_bfloat16 g_B[KCODES * DIM];   // emb as [k][d], bf16

// ---------------- PTX helpers (base sm_103 -- NO tcgen05) ----------------
__device__ __forceinline__ uint32_t smem_u32(const void* p) {
    uint32_t a;
    asm("{ .reg .u64 t; cvta.to.shared.u64 t, %1; cvt.u32.u64 %0, t; }" : "=r"(a) : "l"(p));
    return a;
}

__device__ __forceinline__ void mma_bf16(float* d, const uint32_t* a, const uint32_t* b) {
    asm volatile(
        "mma.sync.aligned.m16n8k16.row.col.f32.bf16.bf16.f32 "
        "{%0,%1,%2,%3}, {%4,%5,%6,%7}, {%8,%9}, {%0,%1,%2,%3};"
        : "+f"(d[0]), "+f"(d[1]), "+f"(d[2]), "+f"(d[3])
        : "r"(a[0]), "r"(a[1]), "r"(a[2]), "r"(a[3]), "r"(b[0]), "r"(b[1]));
}

__device__ __forceinline__ void ldsm_x4(uint32_t* r, uint32_t a) {
    asm volatile("ldmatrix.sync.aligned.m8n8.x4.shared.b16 {%0,%1,%2,%3}, [%4];"
                 : "=r"(r[0]), "=r"(r[1]), "=r"(r[2]), "=r"(r[3]) : "r"(a));
}

#define CP_ASYNC16(dst, src) \
    asm volatile("cp.async.cg.shared.global [%0], [%1], 16;" :: "r"(dst), "l"(src))
#define CP_COMMIT() asm volatile("cp.async.commit_group;" ::: "memory")
#define CP_WAIT(n)  asm volatile("cp.async.wait_group %0;" :: "n"(n) : "memory")

// packed f32x2 fma (two independent IEEE fp32 fma.rn lanes)
#define FMA2(acc, a, b) \
    asm("fma.rn.f32x2 %0, %1, %2, %0;" : "+l"(acc) : "l"(a), "l"(b))

__device__ __forceinline__ unsigned long long dup2(float f) {
    unsigned long long r;
    asm("mov.b64 %0, {%1, %1};" : "=l"(r) : "f"(f));
    return r;
}
__device__ __forceinline__ void unpack2(float& lo, float& hi, unsigned long long v) {
    asm("mov.b64 {%0, %1}, %2;" : "=f"(lo), "=f"(hi) : "l"(v));
}
// monotone float->uint map; key = (mapped score << 32) | k  => min key = min
// score with first-index tiebreak.
__device__ __forceinline__ unsigned long long packkey(float s, int k) {
    unsigned u = __float_as_uint(s);
    u = (u & 0x80000000u) ? ~u : (u | 0x80000000u);
    return ((unsigned long long)u << 32) | (unsigned)k;
}

// ---------------- smem layout for k_argmin_mma (dynamic) ----------------
// A rows are 512B (256 bf16); B stage rows are 256B (128 bf16, one K-half).
// swizzle: byte_in_row ^= (row&7)<<4 (16B granularity)
#define SM_A    0                    // 128 x 512B = 65536
#define SM_B0   65536                // 256 x 256B = 65536 (K-half stage)
#define SM_B1   131072               // 64KB stage
#define SMEM_TOTAL_MMA 196608
// merge scratch reuses SM_B0 region after the main loop:
#define SM_MB1  65536                // float [128*4]
#define SM_MI1  (65536 + 2048)       // int   [128*4]
#define SM_MB2  (65536 + 4096)       // float [128*4]

// ---------------- kernel: zero scratch (graph-replay safe) ----------------
__global__ void k_zero() {
    int i = blockIdx.x * blockDim.x + threadIdx.x;   // covers KCODES*DIM
    g_dw[i] = 0.f;
    if (i < KCODES) g_count[i] = 0.f;
    if (i < NPTS) g_best[i] = ~0ull;
    if (i == 0) { g_loss = 0.f; g_nflag = 0; }
}

// ---------------- kernel: code norms ||e_k||^2 ----------------
__global__ void k_cnorm(const float* __restrict__ emb) {
    int w = (blockIdx.x * blockDim.x + threadIdx.x) >> 5;
    int lane = threadIdx.x & 31;
    if (w >= KCODES) return;
    const float4* r = reinterpret_cast<const float4*>(emb + (size_t)w * DIM);
    float s = 0.f;
#pragma unroll
    for (int q = 0; q < 2; q++) {
        float4 v = r[lane + 32 * q];
        s += v.x * v.x + v.y * v.y + v.z * v.z + v.w * v.w;
    }
#pragma unroll
    for (int off = 16; off; off >>= 1) s += __shfl_xor_sync(0xffffffffu, s, off);
    if (lane == 0) g_cnorm[w] = s;
}

// ---------------- kernel: point norms ||x_n||^2 (near-exact, for rescue) ----
__global__ void k_xnorm(const float* __restrict__ x) {
    int n = blockIdx.x * 256 + threadIdx.x;
    int b = n >> 10, s = n & 1023;
    const float* xb = x + (size_t)b * XSTRIDE_B + s;
    double acc = 0.0;
#pragma unroll 8
    for (int d = 0; d < DIM; d++) {
        float v = xb[(size_t)d * SPATIAL];
        acc += (double)v * (double)v;
    }
    g_xnorm[n] = (float)acc;
}

// ---------------- kernel: emb -> bf16 [k][d] ----------------
__global__ void k_split_e(const float* __restrict__ emb) {
    int i = blockIdx.x * 256 + threadIdx.x;          // KCODES*64 threads
    int row = i >> 6, c0 = (i & 63) * 4;
    float4 v = *reinterpret_cast<const float4*>(emb + (size_t)row * DIM + c0);
    float vv[4] = {v.x, v.y, v.z, v.w};
    unsigned short hs[4];
#pragma unroll
    for (int q = 0; q < 4; q++) hs[q] = __bfloat16_as_ushort(__float2bfloat16(vv[q]));
    *reinterpret_cast<uint2*>(&g_B[(size_t)row * DIM + c0]) = *reinterpret_cast<uint2*>(hs);
}

// ---------------- kernel: x transpose -> bf16 A [n][d] ----------------
__global__ void k_split_x(const float* __restrict__ x) {
    __shared__ float tile[16][68];
    const int n0 = blockIdx.x * 64;                  // 64 points per block
    const int b = n0 >> 10, s0 = n0 & 1023;
    const int t = threadIdx.x;
    const int di = t >> 4, sq = (t & 15) * 4;        // read role
    const int nl = t & 63, dg = t >> 6;              // write role (4 dims each)

    for (int dc = 0; dc < 16; dc++) {
        int d0 = dc * 16;
        float4 v = *reinterpret_cast<const float4*>(
            x + (size_t)b * XSTRIDE_B + (size_t)(d0 + di) * SPATIAL + s0 + sq);
        tile[di][sq + 0] = v.x; tile[di][sq + 1] = v.y;
        tile[di][sq + 2] = v.z; tile[di][sq + 3] = v.w;
        __syncthreads();
        unsigned short hs[4];
#pragma unroll
        for (int q = 0; q < 4; q++)
            hs[q] = __bfloat16_as_ushort(__float2bfloat16(tile[dg * 4 + q][nl]));
        *reinterpret_cast<uint2*>(&g_A[(size_t)(n0 + nl) * DIM + d0 + dg * 4]) =
            *reinterpret_cast<uint2*>(hs);
        __syncthreads();
    }
}

// ---------------- kernel: bf16 mma.sync GEMM + argmin + margin flag ---------
// 256 threads, warp grid 2(M) x 4(N), warp tile 64x64 (mt=4, nt=8).
// Code tiles of 256; K=256 streamed as two 128-dim halves (64KB stages,
// double-buffered). Per k-step: 8 ldsm feed 32 mma -> 128 B LDS per mma.
// K accumulation order s=0..15 preserved -> scores bit-identical to R13.
__global__ __launch_bounds__(256, 1)
void k_argmin_mma() {
    extern __shared__ char sm[];
    const uint32_t smb = smem_u32(sm);
    const int tid = threadIdx.x;
    const int w = tid >> 5, l = tid & 31;
    const int wm = w & 1, wn = w >> 1;           // 2 x 4
    const int n0 = blockIdx.x * 128;

    // ---- load resident A: 128 rows x 512B, swizzled ----
#pragma unroll
    for (int q = 0; q < 16; q++) {
        int idx = tid + 256 * q;                 // uint4 index (4096 total)
        int row = idx >> 5;
        int kb = (idx & 31) * 16;
        uint4 v = *reinterpret_cast<const uint4*>(&g_A[(size_t)(n0 + row) * DIM + (kb >> 1)]);
        *reinterpret_cast<uint4*>(sm + SM_A + row * 512 + (kb ^ ((row & 7) << 4))) = v;
    }

    // B chunk loader: chunk c = (code tile c>>1, K-half c&1); 256 rows x 256B
    auto loadB = [&](int c, uint32_t stg) {
        const char* src = (const char*)(g_B)
            + (size_t)(c >> 1) * 256 * 512 + (size_t)(c & 1) * 256;
#pragma unroll
        for (int q = 0; q < 16; q++) {
            int idx = tid + 256 * q;             // 4096 16B-chunks
            int row = idx >> 4;                  // 0..255
            int kb = (idx & 15) * 16;            // 0..240
            CP_ASYNC16(smb + stg + row * 256 + (kb ^ ((row & 7) << 4)),
                       src + (size_t)row * 512 + kb);
        }
    };

    // prologue: chunk 0 -> stage 0
    loadB(0, SM_B0);
    CP_COMMIT();

    const float INF = __int_as_float(0x7f800000);
    float best1[8], best2[8];
    int   idx1[8];
#pragma unroll
    for (int rs = 0; rs < 8; rs++) { best1[rs] = INF; best2[rs] = INF; idx1[rs] = 0; }

    // invariant ldmatrix address pieces
    const int arow_base = wm * 64 + (l & 15);
    const int axk = ((l >> 4) & 1) * 16;         // A k-byte offset within step
    const int brow_base = wn * 64 + ((l >> 4) & 1) * 8 + (l & 7);
    const int bxk = ((l >> 3) & 1) * 16;         // B k-byte offset within step

    float acc[4][8][4];

#pragma unroll 1
    for (int c = 0; c < 64; c++) {
        if (c + 1 < 64) {
            loadB(c + 1, ((c + 1) & 1) ? SM_B1 : SM_B0);
            CP_COMMIT();
            CP_WAIT(1);
        } else {
            CP_WAIT(0);
        }
        __syncthreads();

        const uint32_t bb = smb + ((c & 1) ? SM_B1 : SM_B0);
        const int kh = c & 1;

        if (kh == 0) {
#pragma unroll
            for (int mt = 0; mt < 4; mt++)
#pragma unroll
                for (int nt = 0; nt < 8; nt++)
#pragma unroll
                    for (int j = 0; j < 4; j++) acc[mt][nt][j] = 0.f;
        }

#pragma unroll 2
        for (int ss = 0; ss < 8; ss++) {
            const int kbA = (kh * 8 + ss) * 32;  // A: full 512B rows
            const int kbB = ss * 32;             // B stage: 256B rows
            uint32_t afr[4][4];
#pragma unroll
            for (int mt = 0; mt < 4; mt++) {
                int row = arow_base + mt * 16;
                ldsm_x4(afr[mt], smb + SM_A + row * 512 + ((kbA + axk) ^ ((row & 7) << 4)));
            }
            uint32_t bfr[8][2];
#pragma unroll
            for (int np = 0; np < 4; np++) {
                int rb = brow_base + np * 16;
                uint32_t r4[4];
                ldsm_x4(r4, bb + rb * 256 + ((kbB + bxk) ^ ((rb & 7) << 4)));
                bfr[np * 2][0] = r4[0]; bfr[np * 2][1] = r4[1];
                bfr[np * 2 + 1][0] = r4[2]; bfr[np * 2 + 1][1] = r4[3];
            }
#pragma unroll
            for (int mt = 0; mt < 4; mt++)
#pragma unroll
                for (int nt = 0; nt < 8; nt++)
                    mma_bf16(acc[mt][nt], afr[mt], bfr[nt]);
        }
        __syncthreads();   // compute done before next iter's cp.async overwrites

        if (kh == 1) {
            // ---- epilogue for code tile it = c>>1 (256 codes) ----
            const float* cn = g_cnorm + (c >> 1) * 256 + wn * 64;
            float cnv[16];
#pragma unroll
            for (int nt = 0; nt < 8; nt++)
#pragma unroll
                for (int jl = 0; jl < 2; jl++)
                    cnv[nt * 2 + jl] = __ldg(&cn[nt * 8 + 2 * (l & 3) + jl]);

            const int cibase = (c >> 1) * 256 + wn * 64;
#pragma unroll
            for (int mt = 0; mt < 4; mt++)
#pragma unroll
                for (int jh = 0; jh < 2; jh++) {
                    const int rs = mt * 2 + jh;
                    float b1 = best1[rs], b2 = best2[rs];
                    int i1 = idx1[rs];
#pragma unroll
                    for (int nt = 0; nt < 8; nt++)
#pragma unroll
                        for (int jl = 0; jl < 2; jl++) {
                            float s = fmaf(-2.f, acc[mt][nt][jh * 2 + jl], cnv[nt * 2 + jl]);
                            int ci = cibase + nt * 8 + 2 * (l & 3) + jl;
                            if (s < b1) { b2 = b1; b1 = s; i1 = ci; }
                            else if (s < b2) b2 = s;
                        }
                    best1[rs] = b1; best2[rs] = b2; idx1[rs] = i1;
                }
        }
    }

    // ---- quad reduce (lanes l^1, l^2 share rows, hold different cols) ----
#pragma unroll
    for (int off = 1; off <= 2; off <<= 1) {
#pragma unroll
        for (int rs = 0; rs < 8; rs++) {
            float ob1 = __shfl_xor_sync(0xffffffffu, best1[rs], off);
            int   oi1 = __shfl_xor_sync(0xffffffffu, idx1[rs], off);
            float ob2 = __shfl_xor_sync(0xffffffffu, best2[rs], off);
            if (ob1 < best1[rs]) {
                best2[rs] = fminf(best1[rs], ob2);
                best1[rs] = ob1; idx1[rs] = oi1;
            } else {
                best2[rs] = fminf(best2[rs], ob1);
            }
        }
    }

    // ---- cross-warp merge (4 wn groups) via smem (reuse stage 0 space) ----
    float* MB1 = reinterpret_cast<float*>(sm + SM_MB1);
    int*   MI1 = reinterpret_cast<int*>(sm + SM_MI1);
    float* MB2 = reinterpret_cast<float*>(sm + SM_MB2);
    if ((l & 3) == 0) {
#pragma unroll
        for (int rs = 0; rs < 8; rs++) {
            int mt = rs >> 1, jh = rs & 1;
            int row = wm * 64 + mt * 16 + jh * 8 + (l >> 2);
            MB1[row * 4 + wn] = best1[rs];
            MI1[row * 4 + wn] = idx1[rs];
            MB2[row * 4 + wn] = best2[rs];
        }
    }
    __syncthreads();
    if (tid < 128) {
        int row = tid;
        float b1 = MB1[row * 4]; int i1 = MI1[row * 4]; float b2 = MB2[row * 4];
#pragma unroll
        for (int g = 1; g < 4; g++) {
            float ob1 = MB1[row * 4 + g];
            int   oi1 = MI1[row * 4 + g];
            float ob2 = MB2[row * 4 + g];
            if (ob1 < b1) { b2 = fminf(b1, ob2); b1 = ob1; i1 = oi1; }
            else          { b2 = fminf(b2, ob1); }
        }
        int n = n0 + row;
        g_idx[n] = i1;
        g_flag[n] = (b2 - b1 < RESCUE_EPS) ? 1 : 0;
    }
}

// ---------------- kernel: compact flagged points into a list ----------------
__global__ void k_compact() {
    int n = blockIdx.x * 256 + threadIdx.x;
    if (g_flag[n]) {
        int p = atomicAdd(&g_nflag, 1);
        g_list[p] = n;
    }
}

// ---------------- kernel: exact-fp32 rescue, f32x2, x reused across codes ---
// Unit = (batch of 8 points, slice of 2048 codes). Each thread handles 8 codes
// in 4 groups of 2; x is loaded once per (j,ll) via LDS.128 and reused across
// both codes -> LDS:FMA2 drops from 1:1 to 1:4. Per-(point,code) arithmetic is
// lane-for-lane identical to the proven path: 4 dim-partitioned fp32
// accumulators (dim d -> lane d&3, j ascending), dot = (d0+d1)+(d2+d3),
// score = fl(fl(A - 2*dot) + ||e||^2). Merge via atomicMin on packed keys.
__global__ __launch_bounds__(256)
void k_rescue2(const float* __restrict__ x, const float* __restrict__ emb) {
    __shared__ __align__(16) float xsT[DIM][8];   // [d][point], 8 KB
    __shared__ int pn[8];
    __shared__ unsigned long long wmin[8][8];     // [point][warp]
    const int t = threadIdx.x;
    const int nf = g_nflag;
    const int nbatch = (nf + 7) >> 3;
    const int nunits = nbatch * 4;

    for (int u = blockIdx.x; u < nunits; u += gridDim.x) {
        const int bi = u >> 2, sl = u & 3;
        const int base = bi * 8;
        const int cnt = min(8, nf - base);
        if (t < 8) pn[t] = g_list[base + min(t, cnt - 1)];
        for (int q = t; q < DIM * 8; q += 256)
            (&xsT[0][0])[q] = 0.f;
        __syncthreads();
        for (int q = t; q < cnt * DIM; q += 256) {
            int p = q >> 8, d = q & 255;
            int n = pn[p];
            xsT[d][p] = x[(size_t)(n >> 10) * XSTRIDE_B + (size_t)d * SPATIAL + (n & 1023)];
        }
        __syncthreads();

        float Ap[8];
#pragma unroll
        for (int p = 0; p < 8; p++) Ap[p] = (p < cnt) ? g_xnorm[pn[p]] : 0.f;

        unsigned long long bk[8];
#pragma unroll
        for (int p = 0; p < 8; p++) bk[p] = ~0ull;

#pragma unroll 1
        for (int g = 0; g < 4; g++) {
            const int k0 = sl * 2048 + g * 512 + t;
            const float4* er0 = reinterpret_cast<const float4*>(emb + (size_t)k0 * DIM);
            const float4* er1 = reinterpret_cast<const float4*>(emb + (size_t)(k0 + 256) * DIM);
            unsigned long long acc2[2][4][4];     // [code][lane d&3][point pair]
#pragma unroll
            for (int cc = 0; cc < 2; cc++)
#pragma unroll
                for (int ll = 0; ll < 4; ll++)
#pragma unroll
                    for (int pr = 0; pr < 4; pr++) acc2[cc][ll][pr] = 0ull;

#pragma unroll 4
            for (int j = 0; j < 64; j++) {
                unsigned long long xv[4][4];
#pragma unroll
                for (int ll = 0; ll < 4; ll++) {
                    ulonglong2 a = *reinterpret_cast<const ulonglong2*>(&xsT[4 * j + ll][0]);
                    ulonglong2 b = *reinterpret_cast<const ulonglong2*>(&xsT[4 * j + ll][4]);
                    xv[ll][0] = a.x; xv[ll][1] = a.y; xv[ll][2] = b.x; xv[ll][3] = b.y;
                }
#pragma unroll
                for (int cc = 0; cc < 2; cc++) {
                    float4 e = (cc ? er1 : er0)[j];
                    unsigned long long ed[4] = {dup2(e.x), dup2(e.y), dup2(e.z), dup2(e.w)};
#pragma unroll
                    for (int ll = 0; ll < 4; ll++) {
                        FMA2(acc2[cc][ll][0], ed[ll], xv[ll][0]);
                        FMA2(acc2[cc][ll][1], ed[ll], xv[ll][1]);
                        FMA2(acc2[cc][ll][2], ed[ll], xv[ll][2]);
                        FMA2(acc2[cc][ll][3], ed[ll], xv[ll][3]);
                    }
                }
            }
#pragma unroll
            for (int cc = 0; cc < 2; cc++) {
                const int k = k0 + cc * 256;
                const float cn = g_cnorm[k];
#pragma unroll
                for (int p = 0; p < 8; p++) {
                    int pr = p >> 1, hi = p & 1;
                    float d0l, d0h, d1l, d1h, d2l, d2h, d3l, d3h;
                    unpack2(d0l, d0h, acc2[cc][0][pr]);
                    unpack2(d1l, d1h, acc2[cc][1][pr]);
                    unpack2(d2l, d2h, acc2[cc][2][pr]);
                    unpack2(d3l, d3h, acc2[cc][3][pr]);
                    float d0 = hi ? d0h : d0l, d1 = hi ? d1h : d1l;
                    float d2 = hi ? d2h : d2l, d3 = hi ? d3h : d3l;
                    float dot = (d0 + d1) + (d2 + d3);
                    float sc = __fadd_rn(__fadd_rn(Ap[p], __fmul_rn(-2.0f, dot)), cn);
                    unsigned long long key = packkey(sc, k);
                    if (key < bk[p]) bk[p] = key;
                }
            }
        }

        // warp min, then block merge, then one atomicMin per point
#pragma unroll
        for (int off = 16; off; off >>= 1)
#pragma unroll
            for (int p = 0; p < 8; p++) {
                unsigned long long ok = __shfl_down_sync(0xffffffffu, bk[p], off);
                if (ok < bk[p]) bk[p] = ok;
            }
        const int wid = t >> 5;
        if ((t & 31) == 0) {
#pragma unroll
            for (int p = 0; p < 8; p++) wmin[p][wid] = bk[p];
        }
        __syncthreads();
        if (t < cnt) {
            unsigned long long m = wmin[t][0];
#pragma unroll
            for (int ww = 1; ww < 8; ww++) m = min(m, wmin[t][ww]);
            atomicMin(&g_best[pn[t]], m);
        }
        __syncthreads();   // protect xsT/pn before next unit
    }
}

// ---------------- kernel: finalize rescued indices + counts ----------------
__global__ void k_count() {
    int i = blockIdx.x * 256 + threadIdx.x;
    int idx = g_idx[i];
    if (g_flag[i]) {
        idx = (int)(g_best[i] & 0xffffffffu);
        g_idx[i] = idx;
    }
    atomicAdd(&g_count[idx], 1.0f);
}

// ---------------- kernel: dw[k][d] += flat[n][d] scatter ----------------
__global__ void k_dw(const float* __restrict__ x) {
    const int n0 = blockIdx.x * 64;
    const int b = n0 >> 10, s0 = n0 & 1023;
    const int t = threadIdx.x;
    const int p = t & 63;
    const int dg = t >> 6;
    const int kidx = g_idx[n0 + p];
    const float* xb = x + (size_t)b * XSTRIDE_B + s0 + p;
    float* dwr = g_dw + (size_t)kidx * DIM;
#pragma unroll 4
    for (int dd = 0; dd < 64; dd++) {
        int d = dg + 4 * dd;
        atomicAdd(&dwr[d], xb[(size_t)d * SPATIAL]);
    }
}

// ---------------- kernel: EMA update + normalized embedding ----------------
__global__ void k_ema(const float* __restrict__ cs, const float* __restrict__ eavg,
                      float* __restrict__ out) {
    const int idx = blockIdx.x * blockDim.x + threadIdx.x;
    const int k = idx >> 8;
    const float ncs = cs[k] * 0.99f + 0.01f * g_count[k];
    const float na = eavg[idx] * 0.99f + 0.01f * g_dw[idx];
    out[EAVG_OFF + idx] = na;
    out[EMB_OFF + idx] = na / fmaxf(ncs, 1e-5f);
    if ((idx & 255) == 0) out[CS_OFF + k] = ncs;
}

// ---------------- kernel: quantized output (x layout) + loss ----------------
__global__ void k_quant(const float* __restrict__ x, const float* __restrict__ emb,
                        float* __restrict__ out) {
    __shared__ float sq[32][257];
    __shared__ float red[8];
    const int n0 = blockIdx.x * 32;
    const int b = n0 >> 10, s0 = n0 & 1023;
    const int t = threadIdx.x;

    {
        int s = t >> 3;
        int c0 = (t & 7) * 32;
        int kidx = g_idx[n0 + s];
        const float4* er = reinterpret_cast<const float4*>(emb + (size_t)kidx * DIM + c0);
#pragma unroll
        for (int q = 0; q < 8; q++) {
            float4 v = er[q];
            sq[s][c0 + 4 * q + 0] = v.x;
            sq[s][c0 + 4 * q + 1] = v.y;
            sq[s][c0 + 4 * q + 2] = v.z;
            sq[s][c0 + 4 * q + 3] = v.w;
        }
    }
    __syncthreads();

    const int s2 = t & 31;
    const int cg = t >> 5;
    const float* xr = x + (size_t)b * XSTRIDE_B + s0 + s2;
    float* ob = out + (size_t)b * XSTRIDE_B + s0 + s2;
    float ls = 0.f;
#pragma unroll 8
    for (int cc = 0; cc < 32; cc++) {
        int c = cg + 8 * cc;
        float q = sq[s2][c];
        float xv = xr[(size_t)c * SPATIAL];
        ob[(size_t)c * SPATIAL] = __fadd_rn(xv, __fsub_rn(q, xv));
        float d = xv - q;
        ls = fmaf(d, d, ls);
    }
#pragma unroll
    for (int off = 16; off; off >>= 1) ls += __shfl_xor_sync(0xffffffffu, ls, off);
    int lane = t & 31, ww = t >> 5;
    if (lane == 0) red[ww] = ls;
    __syncthreads();
    if (t == 0) {
        float tot = 0.f;
#pragma unroll
        for (int q = 0; q < 8; q++) tot += red[q];
        atomicAdd(&g_loss, tot);
    }
}

// ---------------- kernel: finalize loss + perplexity ----------------
__global__ void k_final(float* __restrict__ out) {
    __shared__ float red[8];
    const int t = threadIdx.x;
    float s = 0.f;
#pragma unroll
    for (int q = 0; q < 32; q++) {
        int k = t + 256 * q;
        float p = g_count[k] * (1.f / 16384.f);
        s += p * logf(p + 1e-10f);
    }
#pragma unroll
    for (int off = 16; off; off >>= 1) s += __shfl_xor_sync(0xffffffffu, s, off);
    int lane = t & 31, ww = t >> 5;
    if (lane == 0) red[ww] = s;
    __syncthreads();
    if (t == 0) {
        float tot = 0.f;
#pragma unroll
        for (int q = 0; q < 8; q++) tot += red[q];
        out[PPL_OFF] = expf(-tot);
        out[LOSS_OFF] = 0.25f * g_loss * (1.f / 4194304.f);
    }
}

// ---------------- launch ----------------
// Ordered so k_argmin_mma is the 4th launch (the one the ncu window captures).
extern "C" void kernel_launch(void* const* d_in, const int* in_sizes, int n_in,
                              void* d_out, int out_size) {
    const float* x    = (const float*)d_in[0];
    const float* emb  = (const float*)d_in[1];
    const float* cs   = (const float*)d_in[2];
    const float* eavg = (const float*)d_in[3];
    float* out = (float*)d_out;

    cudaFuncSetAttribute(k_argmin_mma, cudaFuncAttributeMaxDynamicSharedMemorySize,
                         SMEM_TOTAL_MMA);

    k_cnorm  <<<(KCODES * 32) / 256, 256>>>(emb);          // 1
    k_split_e<<<(KCODES * 64) / 256, 256>>>(emb);          // 2
    k_split_x<<<NPTS / 64, 256>>>(x);                      // 3
    k_argmin_mma<<<NPTS / 128, 256, SMEM_TOTAL_MMA>>>();   // 4  <-- profiled
    k_zero   <<<(KCODES * DIM) / 256, 256>>>();            // 5
    k_xnorm  <<<NPTS / 256, 256>>>(x);                     // 6
    k_compact<<<NPTS / 256, 256>>>();                      // 7
    k_rescue2<<<1024, 256>>>(x, emb);                      // 8
    k_count  <<<NPTS / 256, 256>>>();                      // 9
    k_dw     <<<NPTS / 64, 256>>>(x);                      // 10
    k_ema    <<<(KCODES * DIM) / 256, 256>>>(cs, eavg, out); // 11
    k_quant  <<<NPTS / 32, 256>>>(x, emb, out);            // 12
    k_final  <<<1, 256>>>(out);                            // 13
}

// round 16
// speedup vs baseline: 1.7562x; 1.7562x over previous
#include <cuda_runtime.h>
#include <cuda_bf16.h>
#include <cstdint>

// ---------------- problem constants ----------------
#define NPTS     16384          // 16 * 32 * 32 points
#define DIM      256            // embedding dim (channels)
#define KCODES   8192           // codebook size
#define XSTRIDE_B 262144        // 256 * 1024 floats per batch in x layout
#define SPATIAL  1024           // 32*32

// output packing (tuple order, flattened)
#define LOSS_OFF 4194304u
#define PPL_OFF  4194305u
#define EMB_OFF  4194306u
#define CS_OFF   6291458u
#define EAVG_OFF 6299650u

// margin threshold for exact-fp32 rescue (0.05 ~ 5 sigma; 0.02 leaked one flip)
#define RESCUE_EPS 0.05f

// ---------------- scratch (no allocations allowed) ----------------
__device__ int   g_idx[NPTS];
__device__ int   g_flag[NPTS];
__device__ int   g_nflag;
__device__ int   g_list[NPTS];
__device__ unsigned long long g_best[NPTS];
__device__ float g_count[KCODES];
__device__ float g_dw[KCODES * DIM];
__device__ float g_cnorm[KCODES];
__device__ float g_xnorm[NPTS];
__device__ float g_loss;
__device__ __nv_bfloat16 g_A[NPTS * DIM];     // x transposed to [n][d], bf16
__device__ __nv_bfloat16 g_B[KCODES * DIM];   // emb as [k][d], bf16

// ---------------- PTX helpers (base sm_103 -- NO tcgen05) ----------------
__device__ __forceinline__ uint32_t smem_u32(const void* p) {
    uint32_t a;
    asm("{ .reg .u64 t; cvta.to.shared.u64 t, %1; cvt.u32.u64 %0, t; }" : "=r"(a) : "l"(p));
    return a;
}

__device__ __forceinline__ void mma_bf16(float* d, const uint32_t* a, const uint32_t* b) {
    asm volatile(
        "mma.sync.aligned.m16n8k16.row.col.f32.bf16.bf16.f32 "
        "{%0,%1,%2,%3}, {%4,%5,%6,%7}, {%8,%9}, {%0,%1,%2,%3};"
        : "+f"(d[0]), "+f"(d[1]), "+f"(d[2]), "+f"(d[3])
        : "r"(a[0]), "r"(a[1]), "r"(a[2]), "r"(a[3]), "r"(b[0]), "r"(b[1]));
}

__device__ __forceinline__ void ldsm_x4(uint32_t* r, uint32_t a) {
    asm volatile("ldmatrix.sync.aligned.m8n8.x4.shared.b16 {%0,%1,%2,%3}, [%4];"
                 : "=r"(r[0]), "=r"(r[1]), "=r"(r[2]), "=r"(r[3]) : "r"(a));
}

#define CP_ASYNC16(dst, src) \
    asm volatile("cp.async.cg.shared.global [%0], [%1], 16;" :: "r"(dst), "l"(src))
#define CP_COMMIT() asm volatile("cp.async.commit_group;" ::: "memory")
#define CP_WAIT(n)  asm volatile("cp.async.wait_group %0;" :: "n"(n) : "memory")

// packed f32x2 fma (two independent IEEE fp32 fma.rn lanes)
#define FMA2(acc, a, b) \
    asm("fma.rn.f32x2 %0, %1, %2, %0;" : "+l"(acc) : "l"(a), "l"(b))

__device__ __forceinline__ unsigned long long dup2(float f) {
    unsigned long long r;
    asm("mov.b64 %0, {%1, %1};" : "=l"(r) : "f"(f));
    return r;
}
__device__ __forceinline__ void unpack2(float& lo, float& hi, unsigned long long v) {
    asm("mov.b64 {%0, %1}, %2;" : "=f"(lo), "=f"(hi) : "l"(v));
}
// monotone float->uint map; key = (mapped score << 32) | k  => min key = min
// score with first-index tiebreak.
__device__ __forceinline__ unsigned long long packkey(float s, int k) {
    unsigned u = __float_as_uint(s);
    u = (u & 0x80000000u) ? ~u : (u | 0x80000000u);
    return ((unsigned long long)u << 32) | (unsigned)k;
}

// ---------------- smem layout for k_argmin_mma (dynamic) ----------------
// rows are 512B (256 bf16); swizzle: byte_in_row ^= (row&7)<<4 (16B granularity)
#define SM_A    0                    // 128 x 512B = 65536
#define SM_B0   65536                // 64KB
#define SM_B1   131072               // 64KB
#define SM_MB1  196608               // float [128*4]
#define SM_MI1  198656               // int   [128*4]
#define SM_MB2  200704               // float [128*4]
#define SMEM_TOTAL_MMA 202752

// ---------------- kernel: zero scratch (graph-replay safe) ----------------
__global__ void k_zero() {
    int i = blockIdx.x * blockDim.x + threadIdx.x;   // covers KCODES*DIM
    g_dw[i] = 0.f;
    if (i < KCODES) g_count[i] = 0.f;
    if (i < NPTS) g_best[i] = ~0ull;
    if (i == 0) { g_loss = 0.f; g_nflag = 0; }
}

// ---------------- kernel: code norms ||e_k||^2 ----------------
__global__ void k_cnorm(const float* __restrict__ emb) {
    int w = (blockIdx.x * blockDim.x + threadIdx.x) >> 5;
    int lane = threadIdx.x & 31;
    if (w >= KCODES) return;
    const float4* r = reinterpret_cast<const float4*>(emb + (size_t)w * DIM);
    float s = 0.f;
#pragma unroll
    for (int q = 0; q < 2; q++) {
        float4 v = r[lane + 32 * q];
        s += v.x * v.x + v.y * v.y + v.z * v.z + v.w * v.w;
    }
#pragma unroll
    for (int off = 16; off; off >>= 1) s += __shfl_xor_sync(0xffffffffu, s, off);
    if (lane == 0) g_cnorm[w] = s;
}

// ---------------- kernel: point norms ||x_n||^2 (near-exact, for rescue) ----
__global__ void k_xnorm(const float* __restrict__ x) {
    int n = blockIdx.x * 256 + threadIdx.x;
    int b = n >> 10, s = n & 1023;
    const float* xb = x + (size_t)b * XSTRIDE_B + s;
    double acc = 0.0;
#pragma unroll 8
    for (int d = 0; d < DIM; d++) {
        float v = xb[(size_t)d * SPATIAL];
        acc += (double)v * (double)v;
    }
    g_xnorm[n] = (float)acc;
}

// ---------------- kernel: emb -> bf16 [k][d] ----------------
__global__ void k_split_e(const float* __restrict__ emb) {
    int i = blockIdx.x * 256 + threadIdx.x;          // KCODES*64 threads
    int row = i >> 6, c0 = (i & 63) * 4;
    float4 v = *reinterpret_cast<const float4*>(emb + (size_t)row * DIM + c0);
    float vv[4] = {v.x, v.y, v.z, v.w};
    unsigned short hs[4];
#pragma unroll
    for (int q = 0; q < 4; q++) hs[q] = __bfloat16_as_ushort(__float2bfloat16(vv[q]));
    *reinterpret_cast<uint2*>(&g_B[(size_t)row * DIM + c0]) = *reinterpret_cast<uint2*>(hs);
}

// ---------------- kernel: x transpose -> bf16 A [n][d] ----------------
__global__ void k_split_x(const float* __restrict__ x) {
    __shared__ float tile[16][68];
    const int n0 = blockIdx.x * 64;                  // 64 points per block
    const int b = n0 >> 10, s0 = n0 & 1023;
    const int t = threadIdx.x;
    const int di = t >> 4, sq = (t & 15) * 4;        // read role
    const int nl = t & 63, dg = t >> 6;              // write role (4 dims each)

    for (int dc = 0; dc < 16; dc++) {
        int d0 = dc * 16;
        float4 v = *reinterpret_cast<const float4*>(
            x + (size_t)b * XSTRIDE_B + (size_t)(d0 + di) * SPATIAL + s0 + sq);
        tile[di][sq + 0] = v.x; tile[di][sq + 1] = v.y;
        tile[di][sq + 2] = v.z; tile[di][sq + 3] = v.w;
        __syncthreads();
        unsigned short hs[4];
#pragma unroll
        for (int q = 0; q < 4; q++)
            hs[q] = __bfloat16_as_ushort(__float2bfloat16(tile[dg * 4 + q][nl]));
        *reinterpret_cast<uint2*>(&g_A[(size_t)(n0 + nl) * DIM + d0 + dg * 4]) =
            *reinterpret_cast<uint2*>(hs);
        __syncthreads();
    }
}

// ---------------- kernel: bf16 mma.sync GEMM + argmin + margin flag ---------
// (EXACT R13 kernel -- 512 threads, warp grid 4x4, 32x32 warp tiles, 221 us)
__global__ __launch_bounds__(512, 1)
void k_argmin_mma() {
    extern __shared__ char sm[];
    const uint32_t smb = smem_u32(sm);
    const int tid = threadIdx.x;
    const int w = tid >> 5, l = tid & 31;
    const int wm = w & 3, wn = w >> 2;           // 4 x 4
    const int n0 = blockIdx.x * 128;

    // ---- load resident A: 128 rows x 512B, swizzled ----
#pragma unroll
    for (int q = 0; q < 8; q++) {
        int idx = tid + 512 * q;                 // uint4 index (4096 total)
        int row = idx >> 5;
        int kb = (idx & 31) * 16;
        uint4 v = *reinterpret_cast<const uint4*>(&g_A[(size_t)(n0 + row) * DIM + (kb >> 1)]);
        *reinterpret_cast<uint4*>(sm + SM_A + row * 512 + (kb ^ ((row & 7) << 4))) = v;
    }

    // ---- prologue: cp.async B tile 0 ----
    {
        const char* src = (const char*)(g_B);
#pragma unroll
        for (int q = 0; q < 8; q++) {
            int idx = tid + 512 * q;
            int row = idx >> 5;
            int kb = (idx & 31) * 16;
            CP_ASYNC16(smb + SM_B0 + row * 512 + (kb ^ ((row & 7) << 4)),
                       src + (size_t)row * 512 + kb);
        }
        CP_COMMIT();
    }

    const float INF = __int_as_float(0x7f800000);
    float best1[4] = {INF, INF, INF, INF};
    float best2[4] = {INF, INF, INF, INF};
    int   idx1[4]  = {0, 0, 0, 0};

    // invariant ldmatrix address pieces
    const int arow_base = wm * 32 + (l & 15);
    const int axk = ((l >> 4) & 1) * 16;         // A k-byte offset within step
    const int brow_base = wn * 32 + ((l >> 4) & 1) * 8 + (l & 7);
    const int bxk = ((l >> 3) & 1) * 16;         // B k-byte offset within step

#pragma unroll 1
    for (int t = 0; t < 64; t++) {
        if (t + 1 < 64) {
            const char* src = (const char*)(g_B) + (size_t)(t + 1) * 128 * 512;
            uint32_t dst = smb + (((t + 1) & 1) ? SM_B1 : SM_B0);
#pragma unroll
            for (int q = 0; q < 8; q++) {
                int idx = tid + 512 * q;
                int row = idx >> 5;
                int kb = (idx & 31) * 16;
                CP_ASYNC16(dst + row * 512 + (kb ^ ((row & 7) << 4)),
                           src + (size_t)row * 512 + kb);
            }
            CP_COMMIT();
            CP_WAIT(1);
        } else {
            CP_WAIT(0);
        }
        __syncthreads();

        const uint32_t bbase = smb + ((t & 1) ? SM_B1 : SM_B0);

        float acc[2][4][4];
#pragma unroll
        for (int mt = 0; mt < 2; mt++)
#pragma unroll
            for (int nt = 0; nt < 4; nt++)
#pragma unroll
                for (int j = 0; j < 4; j++) acc[mt][nt][j] = 0.f;

#pragma unroll 2
        for (int s = 0; s < 16; s++) {
            const int kb = s * 32;               // bytes: 16 bf16 per k-step
            uint32_t afr[2][4];
#pragma unroll
            for (int mt = 0; mt < 2; mt++) {
                int row = arow_base + mt * 16;
                ldsm_x4(afr[mt], smb + SM_A + row * 512 + ((kb + axk) ^ ((row & 7) << 4)));
            }
            uint32_t bfr[4][2];
#pragma unroll
            for (int np = 0; np < 2; np++) {
                int rb = brow_base + np * 16;
                uint32_t r4[4];
                ldsm_x4(r4, bbase + rb * 512 + ((kb + bxk) ^ ((rb & 7) << 4)));
                bfr[np * 2][0] = r4[0]; bfr[np * 2][1] = r4[1];
                bfr[np * 2 + 1][0] = r4[2]; bfr[np * 2 + 1][1] = r4[3];
            }
#pragma unroll
            for (int mt = 0; mt < 2; mt++)
#pragma unroll
                for (int nt = 0; nt < 4; nt++)
                    mma_bf16(acc[mt][nt], afr[mt], bfr[nt]);
        }
        __syncthreads();   // compute done before next iter's cp.async overwrites

        // ---- epilogue: scores + best/second per row slot ----
        const float* cn = g_cnorm + t * 128 + wn * 32;
        float cnv[8];
#pragma unroll
        for (int nt = 0; nt < 4; nt++)
#pragma unroll
            for (int jl = 0; jl < 2; jl++)
                cnv[nt * 2 + jl] = __ldg(&cn[nt * 8 + 2 * (l & 3) + jl]);

        const int cibase = t * 128 + wn * 32;
#pragma unroll
        for (int mt = 0; mt < 2; mt++)
#pragma unroll
            for (int jh = 0; jh < 2; jh++) {
                const int rs = mt * 2 + jh;
                float b1 = best1[rs], b2 = best2[rs];
                int i1 = idx1[rs];
#pragma unroll
                for (int nt = 0; nt < 4; nt++)
#pragma unroll
                    for (int jl = 0; jl < 2; jl++) {
                        float s = fmaf(-2.f, acc[mt][nt][jh * 2 + jl], cnv[nt * 2 + jl]);
                        int ci = cibase + nt * 8 + 2 * (l & 3) + jl;
                        if (s < b1) { b2 = b1; b1 = s; i1 = ci; }
                        else if (s < b2) b2 = s;
                    }
                best1[rs] = b1; best2[rs] = b2; idx1[rs] = i1;
            }
    }

    // ---- quad reduce (lanes l^1, l^2 share rows, hold different cols) ----
#pragma unroll
    for (int off = 1; off <= 2; off <<= 1) {
#pragma unroll
        for (int rs = 0; rs < 4; rs++) {
            float ob1 = __shfl_xor_sync(0xffffffffu, best1[rs], off);
            int   oi1 = __shfl_xor_sync(0xffffffffu, idx1[rs], off);
            float ob2 = __shfl_xor_sync(0xffffffffu, best2[rs], off);
            if (ob1 < best1[rs]) {
                best2[rs] = fminf(best1[rs], ob2);
                best1[rs] = ob1; idx1[rs] = oi1;
            } else {
                best2[rs] = fminf(best2[rs], ob1);
            }
        }
    }

    // ---- cross-warp merge (4 wn groups) via smem ----
    float* MB1 = reinterpret_cast<float*>(sm + SM_MB1);
    int*   MI1 = reinterpret_cast<int*>(sm + SM_MI1);
    float* MB2 = reinterpret_cast<float*>(sm + SM_MB2);
    if ((l & 3) == 0) {
#pragma unroll
        for (int rs = 0; rs < 4; rs++) {
            int row = wm * 32 + (rs >> 1) * 16 + (rs & 1) * 8 + (l >> 2);
            MB1[row * 4 + wn] = best1[rs];
            MI1[row * 4 + wn] = idx1[rs];
            MB2[row * 4 + wn] = best2[rs];
        }
    }
    __syncthreads();
    if (tid < 128) {
        int row = tid;
        float b1 = MB1[row * 4]; int i1 = MI1[row * 4]; float b2 = MB2[row * 4];
#pragma unroll
        for (int g = 1; g < 4; g++) {
            float ob1 = MB1[row * 4 + g];
            int   oi1 = MI1[row * 4 + g];
            float ob2 = MB2[row * 4 + g];
            if (ob1 < b1) { b2 = fminf(b1, ob2); b1 = ob1; i1 = oi1; }
            else          { b2 = fminf(b2, ob1); }
        }
        int n = n0 + row;
        g_idx[n] = i1;
        g_flag[n] = (b2 - b1 < RESCUE_EPS) ? 1 : 0;
    }
}

// ---------------- kernel: compact flagged points into a list ----------------
__global__ void k_compact() {
    int n = blockIdx.x * 256 + threadIdx.x;
    if (g_flag[n]) {
        int p = atomicAdd(&g_nflag, 1);
        g_list[p] = n;
    }
}

// ---------------- kernel: exact-fp32 rescue, 16 points per codebook sweep ---
// The rescue is L2-BOUND on codebook reads (each batch re-reads all 8 MB of
// emb). 16 points/batch halves that traffic vs 8. Unit = (batch of 16 points,
// slice of 1024 codes); each thread handles ONE code per pass (4 passes).
// Per-(point,code) arithmetic is lane-for-lane identical to the proven path:
// 4 dim-partitioned fp32 accumulators (dim d -> lane d&3, j ascending),
// dot = (d0+d1)+(d2+d3), score = fl(fl(A - 2*dot) + ||e||^2).
// Merge via atomicMin on packed (score,k) keys = first-index tiebreak.
#define RPTS 16
__global__ __launch_bounds__(256)
void k_rescue2(const float* __restrict__ x, const float* __restrict__ emb) {
    __shared__ __align__(16) float xsT[DIM][RPTS];   // [d][point], 16 KB
    __shared__ int pn[RPTS];
    __shared__ unsigned long long wmin[RPTS][8];     // [point][warp]
    const int t = threadIdx.x;
    const int nf = g_nflag;
    const int nbatch = (nf + RPTS - 1) / RPTS;
    const int nunits = nbatch * 8;

    for (int u = blockIdx.x; u < nunits; u += gridDim.x) {
        const int bi = u >> 3, sl = u & 7;           // slice of 1024 codes
        const int base = bi * RPTS;
        const int cnt = min(RPTS, nf - base);
        if (t < RPTS) pn[t] = g_list[base + min(t, cnt - 1)];
        for (int q = t; q < DIM * RPTS; q += 256)
            (&xsT[0][0])[q] = 0.f;
        __syncthreads();
        for (int q = t; q < cnt * DIM; q += 256) {
            int p = q >> 8, d = q & 255;
            int n = pn[p];
            xsT[d][p] = x[(size_t)(n >> 10) * XSTRIDE_B + (size_t)d * SPATIAL + (n & 1023)];
        }
        __syncthreads();

        float Ap[RPTS];
#pragma unroll
        for (int p = 0; p < RPTS; p++) Ap[p] = (p < cnt) ? g_xnorm[pn[p]] : 0.f;

        unsigned long long bk[RPTS];
#pragma unroll
        for (int p = 0; p < RPTS; p++) bk[p] = ~0ull;

#pragma unroll 1
        for (int q = 0; q < 4; q++) {
            const int k = sl * 1024 + q * 256 + t;   // one code per thread
            const float4* er = reinterpret_cast<const float4*>(emb + (size_t)k * DIM);
            unsigned long long acc2[4][RPTS / 2];    // [lane d&3][point pair]
#pragma unroll
            for (int ll = 0; ll < 4; ll++)
#pragma unroll
                for (int pr = 0; pr < RPTS / 2; pr++) acc2[ll][pr] = 0ull;

#pragma unroll 4
            for (int j = 0; j < 64; j++) {
                float4 e = er[j];
                unsigned long long ed[4] = {dup2(e.x), dup2(e.y), dup2(e.z), dup2(e.w)};
#pragma unroll
                for (int ll = 0; ll < 4; ll++) {
                    const unsigned long long* xr =
                        reinterpret_cast<const unsigned long long*>(xsT[4 * j + ll]);
#pragma unroll
                    for (int pr = 0; pr < RPTS / 2; pr++)
                        FMA2(acc2[ll][pr], ed[ll], xr[pr]);
                }
            }
            const float cn = g_cnorm[k];
#pragma unroll
            for (int p = 0; p < RPTS; p++) {
                int pr = p >> 1, hi = p & 1;
                float d0l, d0h, d1l, d1h, d2l, d2h, d3l, d3h;
                unpack2(d0l, d0h, acc2[0][pr]);
                unpack2(d1l, d1h, acc2[1][pr]);
                unpack2(d2l, d2h, acc2[2][pr]);
                unpack2(d3l, d3h, acc2[3][pr]);
                float d0 = hi ? d0h : d0l, d1 = hi ? d1h : d1l;
                float d2 = hi ? d2h : d2l, d3 = hi ? d3h : d3l;
                float dot = (d0 + d1) + (d2 + d3);
                float sc = __fadd_rn(__fadd_rn(Ap[p], __fmul_rn(-2.0f, dot)), cn);
                unsigned long long key = packkey(sc, k);
                if (key < bk[p]) bk[p] = key;
            }
        }

        // warp min, then block merge, then one atomicMin per point
#pragma unroll
        for (int off = 16; off; off >>= 1)
#pragma unroll
            for (int p = 0; p < RPTS; p++) {
                unsigned long long ok = __shfl_down_sync(0xffffffffu, bk[p], off);
                if (ok < bk[p]) bk[p] = ok;
            }
        const int wid = t >> 5;
        if ((t & 31) == 0) {
#pragma unroll
            for (int p = 0; p < RPTS; p++) wmin[p][wid] = bk[p];
        }
        __syncthreads();
        if (t < cnt) {
            unsigned long long m = wmin[t][0];
#pragma unroll
            for (int ww = 1; ww < 8; ww++) m = min(m, wmin[t][ww]);
            atomicMin(&g_best[pn[t]], m);
        }
        __syncthreads();   // protect xsT/pn before next unit
    }
}

// ---------------- kernel: finalize rescued indices + counts ----------------
__global__ void k_count() {
    int i = blockIdx.x * 256 + threadIdx.x;
    int idx = g_idx[i];
    if (g_flag[i]) {
        idx = (int)(g_best[i] & 0xffffffffu);
        g_idx[i] = idx;
    }
    atomicAdd(&g_count[idx], 1.0f);
}

// ---------------- kernel: dw[k][d] += flat[n][d] scatter ----------------
__global__ void k_dw(const float* __restrict__ x) {
    const int n0 = blockIdx.x * 64;
    const int b = n0 >> 10, s0 = n0 & 1023;
    const int t = threadIdx.x;
    const int p = t & 63;
    const int dg = t >> 6;
    const int kidx = g_idx[n0 + p];
    const float* xb = x + (size_t)b * XSTRIDE_B + s0 + p;
    float* dwr = g_dw + (size_t)kidx * DIM;
#pragma unroll 4
    for (int dd = 0; dd < 64; dd++) {
        int d = dg + 4 * dd;
        atomicAdd(&dwr[d], xb[(size_t)d * SPATIAL]);
    }
}

// ---------------- kernel: EMA update + normalized embedding ----------------
__global__ void k_ema(const float* __restrict__ cs, const float* __restrict__ eavg,
                      float* __restrict__ out) {
    const int idx = blockIdx.x * blockDim.x + threadIdx.x;
    const int k = idx >> 8;
    const float ncs = cs[k] * 0.99f + 0.01f * g_count[k];
    const float na = eavg[idx] * 0.99f + 0.01f * g_dw[idx];
    out[EAVG_OFF + idx] = na;
    out[EMB_OFF + idx] = na / fmaxf(ncs, 1e-5f);
    if ((idx & 255) == 0) out[CS_OFF + k] = ncs;
}

// ---------------- kernel: quantized output (x layout) + loss ----------------
__global__ void k_quant(const float* __restrict__ x, const float* __restrict__ emb,
                        float* __restrict__ out) {
    __shared__ float sq[32][257];
    __shared__ float red[8];
    const int n0 = blockIdx.x * 32;
    const int b = n0 >> 10, s0 = n0 & 1023;
    const int t = threadIdx.x;

    {
        int s = t >> 3;
        int c0 = (t & 7) * 32;
        int kidx = g_idx[n0 + s];
        const float4* er = reinterpret_cast<const float4*>(emb + (size_t)kidx * DIM + c0);
#pragma unroll
        for (int q = 0; q < 8; q++) {
            float4 v = er[q];
            sq[s][c0 + 4 * q + 0] = v.x;
            sq[s][c0 + 4 * q + 1] = v.y;
            sq[s][c0 + 4 * q + 2] = v.z;
            sq[s][c0 + 4 * q + 3] = v.w;
        }
    }
    __syncthreads();

    const int s2 = t & 31;
    const int cg = t >> 5;
    const float* xr = x + (size_t)b * XSTRIDE_B + s0 + s2;
    float* ob = out + (size_t)b * XSTRIDE_B + s0 + s2;
    float ls = 0.f;
#pragma unroll 8
    for (int cc = 0; cc < 32; cc++) {
        int c = cg + 8 * cc;
        float q = sq[s2][c];
        float xv = xr[(size_t)c * SPATIAL];
        ob[(size_t)c * SPATIAL] = __fadd_rn(xv, __fsub_rn(q, xv));
        float d = xv - q;
        ls = fmaf(d, d, ls);
    }
#pragma unroll
    for (int off = 16; off; off >>= 1) ls += __shfl_xor_sync(0xffffffffu, ls, off);
    int lane = t & 31, ww = t >> 5;
    if (lane == 0) red[ww] = ls;
    __syncthreads();
    if (t == 0) {
        float tot = 0.f;
#pragma unroll
        for (int q = 0; q < 8; q++) tot += red[q];
        atomicAdd(&g_loss, tot);
    }
}

// ---------------- kernel: finalize loss + perplexity ----------------
__global__ void k_final(float* __restrict__ out) {
    __shared__ float red[8];
    const int t = threadIdx.x;
    float s = 0.f;
#pragma unroll
    for (int q = 0; q < 32; q++) {
        int k = t + 256 * q;
        float p = g_count[k] * (1.f / 16384.f);
        s += p * logf(p + 1e-10f);
    }
#pragma unroll
    for (int off = 16; off; off >>= 1) s += __shfl_xor_sync(0xffffffffu, s, off);
    int lane = t & 31, ww = t >> 5;
    if (lane == 0) red[ww] = s;
    __syncthreads();
    if (t == 0) {
        float tot = 0.f;
#pragma unroll
        for (int q = 0; q < 8; q++) tot += red[q];
        out[PPL_OFF] = expf(-tot);
        out[LOSS_OFF] = 0.25f * g_loss * (1.f / 4194304.f);
    }
}

// ---------------- launch ----------------
// Ordered so k_argmin_mma is the 4th launch (the one the ncu window captures).
extern "C" void kernel_launch(void* const* d_in, const int* in_sizes, int n_in,
                              void* d_out, int out_size) {
    const float* x    = (const float*)d_in[0];
    const float* emb  = (const float*)d_in[1];
    const float* cs   = (const float*)d_in[2];
    const float* eavg = (const float*)d_in[3];
    float* out = (float*)d_out;

    cudaFuncSetAttribute(k_argmin_mma, cudaFuncAttributeMaxDynamicSharedMemorySize,
                         SMEM_TOTAL_MMA);

    k_cnorm  <<<(KCODES * 32) / 256, 256>>>(emb);          // 1
    k_split_e<<<(KCODES * 64) / 256, 256>>>(emb);          // 2
    k_split_x<<<NPTS / 64, 256>>>(x);                      // 3
    k_argmin_mma<<<NPTS / 128, 512, SMEM_TOTAL_MMA>>>();   // 4  <-- profiled
    k_zero   <<<(KCODES * DIM) / 256, 256>>>();            // 5
    k_xnorm  <<<NPTS / 256, 256>>>(x);                     // 6
    k_compact<<<NPTS / 256, 256>>>();                      // 7
    k_rescue2<<<1024, 256>>>(x, emb);                      // 8
    k_count  <<<NPTS / 256, 256>>>();                      // 9
    k_dw     <<<NPTS / 64, 256>>>(x);                      // 10
    k_ema    <<<(KCODES * DIM) / 256, 256>>>(cs, eavg, out); // 11
    k_quant  <<<NPTS / 32, 256>>>(x, emb, out);            // 12
    k_final  <<<1, 256>>>(out);                            // 13
}